// round 13
// baseline (speedup 1.0000x reference)
#include <cuda_runtime.h>
#include <cuda_bf16.h>
#include <math.h>
#include <stdint.h>

// Problem dims (fixed by reference)
#define B_ 2
#define S_ 2048
#define D_ 1024
#define H_ 16
#define W_ 64
#define F_ 4096
#define M_ (B_*S_)   // 4096 rows

// ============================ helpers ============================
__device__ __forceinline__ uint32_t smem_u32(const void* p) {
    uint32_t a;
    asm("{ .reg .u64 t; cvta.to.shared.u64 t, %1; cvt.u32.u64 %0, t; }" : "=r"(a) : "l"(p));
    return a;
}
__device__ __forceinline__ void cp16(uint32_t d, const void* g) {
    asm volatile("cp.async.cg.shared.global [%0], [%1], 16;" :: "r"(d), "l"(g));
}
#define CP_COMMIT() asm volatile("cp.async.commit_group;" ::: "memory")
#define CP_WAIT(N)  asm volatile("cp.async.wait_group %0;" :: "n"(N) : "memory")

__device__ __forceinline__ void ldsm4(uint32_t r[4], uint32_t addr) {
    asm volatile("ldmatrix.sync.aligned.m8n8.x4.shared.b16 {%0,%1,%2,%3}, [%4];"
        : "=r"(r[0]), "=r"(r[1]), "=r"(r[2]), "=r"(r[3]) : "r"(addr));
}
__device__ __forceinline__ void mma_bf16(float d[4], const uint32_t a[4], const uint32_t b[2]) {
    asm volatile("mma.sync.aligned.m16n8k16.row.col.f32.bf16.bf16.f32 "
        "{%0,%1,%2,%3},{%4,%5,%6,%7},{%8,%9},{%0,%1,%2,%3};"
        : "+f"(d[0]), "+f"(d[1]), "+f"(d[2]), "+f"(d[3])
        : "r"(a[0]), "r"(a[1]), "r"(a[2]), "r"(a[3]), "r"(b[0]), "r"(b[1]));
}

// -------- scratch (device globals; no runtime allocation allowed) --------
__device__ float          g_Q   [M_*D_];
__device__ float          g_K   [M_*D_];
__device__ float          g_V   [M_*D_];
__device__ float          g_ATT [M_*D_];
__device__ float          g_PROJ[M_*D_];
__device__ float          g_H1  [M_*D_];
__device__ float          g_FF2 [M_*D_];
__device__ __nv_bfloat16  g_xh  [M_*D_],  g_xl  [M_*D_];
__device__ __nv_bfloat16  g_atth[M_*D_],  g_attl[M_*D_];
__device__ __nv_bfloat16  g_h1h [M_*D_],  g_h1l [M_*D_];
__device__ __nv_bfloat16  g_ff1h[M_*F_],  g_ff1l[M_*F_];
__device__ __nv_bfloat16  g_wqh [D_*D_],  g_wql [D_*D_];
__device__ __nv_bfloat16  g_wkh [D_*D_],  g_wkl [D_*D_];
__device__ __nv_bfloat16  g_wvh [D_*D_],  g_wvl [D_*D_];
__device__ __nv_bfloat16  g_woh [D_*D_],  g_wol [D_*D_];
__device__ __nv_bfloat16  g_w1h [F_*D_],  g_w1l [F_*D_];
__device__ __nv_bfloat16  g_w2h [D_*F_],  g_w2l [D_*F_];

// ===========================================================================
// split fp32 -> (hi, lo) bf16 planes. 4 elements / thread.
// ===========================================================================
__global__ __launch_bounds__(256) void split_bf16(
    const float* __restrict__ x, __nv_bfloat16* __restrict__ h,
    __nv_bfloat16* __restrict__ l, int n4)
{
    int i = blockIdx.x * blockDim.x + threadIdx.x;
    if (i >= n4) return;
    float4 v = reinterpret_cast<const float4*>(x)[i];
    __nv_bfloat16 hv[4], lv[4];
    float vv[4] = {v.x, v.y, v.z, v.w};
#pragma unroll
    for (int t = 0; t < 4; t++) {
        hv[t] = __float2bfloat16(vv[t]);
        lv[t] = __float2bfloat16(vv[t] - __bfloat162float(hv[t]));
    }
    reinterpret_cast<uint2*>(h)[i] = *reinterpret_cast<uint2*>(hv);
    reinterpret_cast<uint2*>(l)[i] = *reinterpret_cast<uint2*>(lv);
}

// ===========================================================================
// transpose + split:  in fp32 [R,C] -> out bf16 [C,R]  (out[n][k] = in[k][n])
// ===========================================================================
__global__ void transpose_split(
    const float* __restrict__ in, __nv_bfloat16* __restrict__ oh,
    __nv_bfloat16* __restrict__ ol, int R, int C)
{
    __shared__ float t[32][33];
    int n0 = blockIdx.x * 32, k0 = blockIdx.y * 32;
    int tx = threadIdx.x, ty = threadIdx.y;
#pragma unroll
    for (int j = 0; j < 32; j += 8)
        t[ty + j][tx] = in[(size_t)(k0 + ty + j) * C + n0 + tx];
    __syncthreads();
#pragma unroll
    for (int j = 0; j < 32; j += 8) {
        float v = t[tx][ty + j];
        __nv_bfloat16 hv = __float2bfloat16(v);
        float r = v - __bfloat162float(hv);
        size_t o = (size_t)(n0 + ty + j) * R + k0 + tx;
        oh[o] = hv;
        ol[o] = __float2bfloat16(r);
    }
}

// ===========================================================================
// HMMA split-bf16 GEMM:  C[M,N] = A[M,K] @ B[N,K]^T + bias
// A as hi/lo bf16 K-major; B as hi/lo bf16 K-major (pre-transposed).
// C = AhBh + AhBl + AlBh  (fp32-grade accuracy, fp32 register accumulators)
// CTA tile 128x128, BK=32, 8 warps (warp tile 32x64), cp.async 2-stage.
// ACT=1: exact-erf GELU.  OUTB=1: write bf16 hi/lo planes; else fp32.
// ===========================================================================
#define TILE_B 10240          // 128 rows * 80 bytes (32 bf16 + 8 pad)
#define STAGE_B (4*TILE_B)    // Ah, Al, Bh, Bl
#define GEMM_SMEM (2*STAGE_B) // 81920

template<int ACT, int OUTB>
__global__ __launch_bounds__(256) void hmma_gemm(
    const __nv_bfloat16* __restrict__ Ah, const __nv_bfloat16* __restrict__ Al,
    const __nv_bfloat16* __restrict__ Bh, const __nv_bfloat16* __restrict__ Bl,
    const float* __restrict__ bias,
    float* __restrict__ Cf, __nv_bfloat16* __restrict__ Chi, __nv_bfloat16* __restrict__ Clo,
    int M, int N, int K)
{
    extern __shared__ char sm[];
    __shared__ float bias_s[128];

    const int tid  = threadIdx.x;
    const int lane = tid & 31;
    const int wid  = tid >> 5;
    const int wm   = wid & 3;      // 4 warps over M (32 rows each)
    const int wn   = wid >> 2;     // 2 warps over N (64 cols each)
    const int m0   = blockIdx.y * 128;
    const int n0   = blockIdx.x * 128;
    const uint32_t sbase = smem_u32(sm);

    if (tid < 128) bias_s[tid] = bias[n0 + tid];

    float d[2][8][4];
#pragma unroll
    for (int i = 0; i < 2; i++)
#pragma unroll
        for (int j = 0; j < 8; j++)
#pragma unroll
            for (int e = 0; e < 4; e++) d[i][j][e] = 0.f;

    const int NC = K >> 5;

    // ---- async stage loader: 4 tiles x 128 rows x 32 bf16 ----
    auto issue = [&](int kc, int s) {
        const int koff = kc * 32;
        const uint32_t st = sbase + s * STAGE_B;
#pragma unroll
        for (int i = 0; i < 2; i++) {
            int idx = tid + i * 256;           // 0..511
            int row = idx >> 2, c16 = idx & 3;
            uint32_t doff = (uint32_t)(row * 80 + c16 * 16);
            size_t ga = (size_t)(m0 + row) * K + koff + c16 * 8;
            size_t gb = (size_t)(n0 + row) * K + koff + c16 * 8;
            cp16(st + doff,              Ah + ga);
            cp16(st + TILE_B + doff,     Al + ga);
            cp16(st + 2 * TILE_B + doff, Bh + gb);
            cp16(st + 3 * TILE_B + doff, Bl + gb);
        }
        CP_COMMIT();
    };

    // ldmatrix lane address components
    const int aRow  = lane & 15;            // rows 0..15 of m16 tile
    const int aKsel = lane >> 4;            // k half
    const int bRow  = (lane & 7) + ((lane >> 4) << 3);  // n within 16-col group
    const int bKsel = (lane >> 3) & 1;      // k half

    auto compute = [&](int s) {
        const uint32_t st = sbase + s * STAGE_B;
#pragma unroll
        for (int kp = 0; kp < 2; kp++) {
            uint32_t ah[2][4], al[2][4], bh[8][2], bl[8][2];
            const uint32_t kcol = (uint32_t)((kp * 2) * 16);
#pragma unroll
            for (int i = 0; i < 2; i++) {
                uint32_t addr = st + (uint32_t)((wm * 32 + i * 16 + aRow) * 80) + kcol + (uint32_t)(aKsel * 16);
                ldsm4(ah[i], addr);
            }
#pragma unroll
            for (int g = 0; g < 4; g++) {
                uint32_t addr = st + 2 * TILE_B + (uint32_t)((wn * 64 + g * 16 + bRow) * 80) + kcol + (uint32_t)(bKsel * 16);
                uint32_t r[4];
                ldsm4(r, addr);
                bh[2*g][0] = r[0]; bh[2*g][1] = r[1];
                bh[2*g+1][0] = r[2]; bh[2*g+1][1] = r[3];
            }
            // pass 1: Ah * Bh
#pragma unroll
            for (int i = 0; i < 2; i++)
#pragma unroll
                for (int j = 0; j < 8; j++) mma_bf16(d[i][j], ah[i], bh[j]);
            // pass 2: Ah * Bl
#pragma unroll
            for (int g = 0; g < 4; g++) {
                uint32_t addr = st + 3 * TILE_B + (uint32_t)((wn * 64 + g * 16 + bRow) * 80) + kcol + (uint32_t)(bKsel * 16);
                uint32_t r[4];
                ldsm4(r, addr);
                bl[2*g][0] = r[0]; bl[2*g][1] = r[1];
                bl[2*g+1][0] = r[2]; bl[2*g+1][1] = r[3];
            }
#pragma unroll
            for (int i = 0; i < 2; i++)
#pragma unroll
                for (int j = 0; j < 8; j++) mma_bf16(d[i][j], ah[i], bl[j]);
            // pass 3: Al * Bh
#pragma unroll
            for (int i = 0; i < 2; i++) {
                uint32_t addr = st + TILE_B + (uint32_t)((wm * 32 + i * 16 + aRow) * 80) + kcol + (uint32_t)(aKsel * 16);
                ldsm4(al[i], addr);
            }
#pragma unroll
            for (int i = 0; i < 2; i++)
#pragma unroll
                for (int j = 0; j < 8; j++) mma_bf16(d[i][j], al[i], bh[j]);
        }
    };

    issue(0, 0);
    for (int kc = 0; kc < NC; kc++) {
        if (kc + 1 < NC) { issue(kc + 1, (kc + 1) & 1); CP_WAIT(1); }
        else             { CP_WAIT(0); }
        __syncthreads();
        compute(kc & 1);
        __syncthreads();
    }

    // ---- epilogue ----
#pragma unroll
    for (int i = 0; i < 2; i++) {
        const int r = m0 + wm * 32 + i * 16 + (lane >> 2);
#pragma unroll
        for (int j = 0; j < 8; j++) {
            const int cl = wn * 64 + j * 8 + 2 * (lane & 3);   // col within 128 tile
            const float b0 = bias_s[cl], b1 = bias_s[cl + 1];
            float v00 = d[i][j][0] + b0, v01 = d[i][j][1] + b1;
            float v10 = d[i][j][2] + b0, v11 = d[i][j][3] + b1;
            if (ACT == 1) {
                v00 = 0.5f * v00 * (1.f + erff(v00 * 0.7071067811865475f));
                v01 = 0.5f * v01 * (1.f + erff(v01 * 0.7071067811865475f));
                v10 = 0.5f * v10 * (1.f + erff(v10 * 0.7071067811865475f));
                v11 = 0.5f * v11 * (1.f + erff(v11 * 0.7071067811865475f));
            }
            const size_t o0 = (size_t)r * N + n0 + cl;
            const size_t o1 = (size_t)(r + 8) * N + n0 + cl;
            if (OUTB) {
                __nv_bfloat16 h00 = __float2bfloat16(v00);
                __nv_bfloat16 h01 = __float2bfloat16(v01);
                __nv_bfloat16 h10 = __float2bfloat16(v10);
                __nv_bfloat16 h11 = __float2bfloat16(v11);
                __nv_bfloat162 hp0; hp0.x = h00; hp0.y = h01;
                __nv_bfloat162 hp1; hp1.x = h10; hp1.y = h11;
                __nv_bfloat162 lp0; lp0.x = __float2bfloat16(v00 - __bfloat162float(h00));
                                    lp0.y = __float2bfloat16(v01 - __bfloat162float(h01));
                __nv_bfloat162 lp1; lp1.x = __float2bfloat16(v10 - __bfloat162float(h10));
                                    lp1.y = __float2bfloat16(v11 - __bfloat162float(h11));
                *reinterpret_cast<__nv_bfloat162*>(Chi + o0) = hp0;
                *reinterpret_cast<__nv_bfloat162*>(Chi + o1) = hp1;
                *reinterpret_cast<__nv_bfloat162*>(Clo + o0) = lp0;
                *reinterpret_cast<__nv_bfloat162*>(Clo + o1) = lp1;
            } else {
                *reinterpret_cast<float2*>(Cf + o0) = make_float2(v00, v01);
                *reinterpret_cast<float2*>(Cf + o1) = make_float2(v10, v11);
            }
        }
    }
}

// ===========================================================================
// Flash-style attention (fp32 SIMT), 2 CTAs/SM.
// ===========================================================================
__global__ __launch_bounds__(256, 2) void attn_kernel(
    const float* __restrict__ Q, const float* __restrict__ K,
    const float* __restrict__ V, const int* __restrict__ mask,
    float* __restrict__ O)
{
    __shared__ float k_s[64][68];
    __shared__ float v_s[64][68];
    __shared__ float madd[64];

    const int tid  = threadIdx.x;
    const int bh   = blockIdx.y;
    const int b    = bh / H_;
    const int h    = bh % H_;
    const int q0   = blockIdx.x * 64;
    const int row  = tid >> 2;
    const int quad = tid & 3;

    float qreg[16];
    {
        const float* qp = Q + (size_t)(b * S_ + q0 + row) * D_ + h * W_ + quad * 16;
#pragma unroll
        for (int t = 0; t < 16; t += 4) {
            float4 f = *reinterpret_cast<const float4*>(qp + t);
            qreg[t] = f.x; qreg[t+1] = f.y; qreg[t+2] = f.z; qreg[t+3] = f.w;
        }
    }

    float o[16];
#pragma unroll
    for (int t = 0; t < 16; t++) o[t] = 0.f;
    float m = -1e30f, l = 0.f;

    for (int kb = 0; kb < S_ / 64; kb++) {
#pragma unroll
        for (int i = 0; i < 16; i++) {
            int idx = tid + i * 256;
            int j = idx >> 6, w = idx & 63;
            size_t goff = (size_t)(b * S_ + kb * 64 + j) * D_ + h * W_ + w;
            k_s[j][w] = K[goff];
            v_s[j][w] = V[goff];
        }
        if (tid < 64)
            madd[tid] = -10000.f * (1.f - (float)mask[b * S_ + kb * 64 + tid]);
        __syncthreads();

#pragma unroll
        for (int c = 0; c < 4; c++) {
            float sj[16];
#pragma unroll
            for (int jj = 0; jj < 16; jj++) {
                int j = c * 16 + jj;
                const float* kr = &k_s[j][quad * 16];
                float pv = 0.f;
#pragma unroll
                for (int t = 0; t < 16; t += 4) {
                    float4 f = *reinterpret_cast<const float4*>(kr + t);
                    pv = fmaf(qreg[t],   f.x, pv);
                    pv = fmaf(qreg[t+1], f.y, pv);
                    pv = fmaf(qreg[t+2], f.z, pv);
                    pv = fmaf(qreg[t+3], f.w, pv);
                }
                pv += __shfl_xor_sync(0xffffffffu, pv, 1);
                pv += __shfl_xor_sync(0xffffffffu, pv, 2);
                sj[jj] = pv * 0.125f + madd[j];
            }
            float mn = m;
#pragma unroll
            for (int jj = 0; jj < 16; jj++) mn = fmaxf(mn, sj[jj]);
            float factor = __expf(m - mn);
            l *= factor;
#pragma unroll
            for (int t = 0; t < 16; t++) o[t] *= factor;
#pragma unroll
            for (int jj = 0; jj < 16; jj++) {
                float pv = __expf(sj[jj] - mn);
                l += pv;
                const float* vr = &v_s[c * 16 + jj][quad * 16];
#pragma unroll
                for (int t = 0; t < 16; t += 4) {
                    float4 f = *reinterpret_cast<const float4*>(vr + t);
                    o[t]   = fmaf(pv, f.x, o[t]);
                    o[t+1] = fmaf(pv, f.y, o[t+1]);
                    o[t+2] = fmaf(pv, f.z, o[t+2]);
                    o[t+3] = fmaf(pv, f.w, o[t+3]);
                }
            }
            m = mn;
        }
        __syncthreads();
    }

    float inv = 1.f / l;
    float* op = O + (size_t)(b * S_ + q0 + row) * D_ + h * W_ + quad * 16;
#pragma unroll
    for (int t = 0; t < 16; t++) op[t] = o[t] * inv;
}

// ===========================================================================
// Fused residual add + LayerNorm. One block (256 thr) per row of 1024.
// ===========================================================================
__global__ __launch_bounds__(256) void add_ln_kernel(
    const float* __restrict__ X, const float* __restrict__ Y,
    const float* __restrict__ gamma, const float* __restrict__ beta,
    float* __restrict__ out)
{
    const int rowbase = blockIdx.x * D_;
    const int tid = threadIdx.x;

    float4 x4 = *reinterpret_cast<const float4*>(X + rowbase + tid * 4);
    float4 y4 = *reinterpret_cast<const float4*>(Y + rowbase + tid * 4);
    float v0 = x4.x + y4.x, v1 = x4.y + y4.y, v2 = x4.z + y4.z, v3 = x4.w + y4.w;

    float s  = v0 + v1 + v2 + v3;
    float sq = v0*v0 + v1*v1 + v2*v2 + v3*v3;

    __shared__ float ssum[8], ssq[8];
#pragma unroll
    for (int off = 16; off; off >>= 1) {
        s  += __shfl_xor_sync(0xffffffffu, s,  off);
        sq += __shfl_xor_sync(0xffffffffu, sq, off);
    }
    int wid = tid >> 5, lane = tid & 31;
    if (lane == 0) { ssum[wid] = s; ssq[wid] = sq; }
    __syncthreads();
    if (tid == 0) {
        float ts = 0.f, tq = 0.f;
#pragma unroll
        for (int i = 0; i < 8; i++) { ts += ssum[i]; tq += ssq[i]; }
        ssum[0] = ts; ssq[0] = tq;
    }
    __syncthreads();

    float mean = ssum[0] * (1.f / D_);
    float var  = ssq[0]  * (1.f / D_) - mean * mean;
    float inv  = rsqrtf(var + 1e-12f);

    float4 g4 = *reinterpret_cast<const float4*>(gamma + tid * 4);
    float4 b4 = *reinterpret_cast<const float4*>(beta  + tid * 4);
    float4 r;
    r.x = g4.x * (v0 - mean) * inv + b4.x;
    r.y = g4.y * (v1 - mean) * inv + b4.y;
    r.z = g4.z * (v2 - mean) * inv + b4.z;
    r.w = g4.w * (v3 - mean) * inv + b4.w;
    *reinterpret_cast<float4*>(out + rowbase + tid * 4) = r;
}

// ===========================================================================
// Launch
// ===========================================================================
template<typename T>
static T* symAddr(const void* sym)
{
    void* p = nullptr;
    cudaGetSymbolAddress(&p, sym);
    return (T*)p;
}

extern "C" void kernel_launch(void* const* d_in, const int* in_sizes, int n_in,
                              void* d_out, int out_size)
{
    const float* x    = (const float*)d_in[0];
    const int*   mask = (const int*)  d_in[1];
    const float* wq   = (const float*)d_in[2];
    const float* bq   = (const float*)d_in[3];
    const float* wk   = (const float*)d_in[4];
    const float* bk   = (const float*)d_in[5];
    const float* wv   = (const float*)d_in[6];
    const float* bv   = (const float*)d_in[7];
    const float* wo   = (const float*)d_in[8];
    const float* bo   = (const float*)d_in[9];
    const float* g1   = (const float*)d_in[10];
    const float* b1   = (const float*)d_in[11];
    const float* w1   = (const float*)d_in[12];
    const float* bf1  = (const float*)d_in[13];
    const float* w2   = (const float*)d_in[14];
    const float* bf2  = (const float*)d_in[15];
    const float* g2   = (const float*)d_in[16];
    const float* b2   = (const float*)d_in[17];
    float* out = (float*)d_out;

    float* Q    = symAddr<float>(g_Q);
    float* K    = symAddr<float>(g_K);
    float* V    = symAddr<float>(g_V);
    float* ATT  = symAddr<float>(g_ATT);
    float* PROJ = symAddr<float>(g_PROJ);
    float* H1   = symAddr<float>(g_H1);
    float* FF2  = symAddr<float>(g_FF2);
    __nv_bfloat16 *xh  = symAddr<__nv_bfloat16>(g_xh),  *xl  = symAddr<__nv_bfloat16>(g_xl);
    __nv_bfloat16 *ath = symAddr<__nv_bfloat16>(g_atth),*atl = symAddr<__nv_bfloat16>(g_attl);
    __nv_bfloat16 *h1h = symAddr<__nv_bfloat16>(g_h1h), *h1l = symAddr<__nv_bfloat16>(g_h1l);
    __nv_bfloat16 *f1h = symAddr<__nv_bfloat16>(g_ff1h),*f1l = symAddr<__nv_bfloat16>(g_ff1l);
    __nv_bfloat16 *wqh = symAddr<__nv_bfloat16>(g_wqh), *wql = symAddr<__nv_bfloat16>(g_wql);
    __nv_bfloat16 *wkh = symAddr<__nv_bfloat16>(g_wkh), *wkl = symAddr<__nv_bfloat16>(g_wkl);
    __nv_bfloat16 *wvh = symAddr<__nv_bfloat16>(g_wvh), *wvl = symAddr<__nv_bfloat16>(g_wvl);
    __nv_bfloat16 *woh = symAddr<__nv_bfloat16>(g_woh), *wol = symAddr<__nv_bfloat16>(g_wol);
    __nv_bfloat16 *w1h = symAddr<__nv_bfloat16>(g_w1h), *w1l = symAddr<__nv_bfloat16>(g_w1l);
    __nv_bfloat16 *w2h = symAddr<__nv_bfloat16>(g_w2h), *w2l = symAddr<__nv_bfloat16>(g_w2l);

    cudaFuncSetAttribute(hmma_gemm<0,0>, cudaFuncAttributeMaxDynamicSharedMemorySize, GEMM_SMEM);
    cudaFuncSetAttribute(hmma_gemm<1,1>, cudaFuncAttributeMaxDynamicSharedMemorySize, GEMM_SMEM);

    dim3 blk(256);
    dim3 t32(32, 8);

    // input / weight conversions
    split_bf16<<<(M_*D_/4 + 255)/256, blk>>>(x, xh, xl, M_*D_/4);
    transpose_split<<<dim3(D_/32, D_/32), t32>>>(wq, wqh, wql, D_, D_);
    transpose_split<<<dim3(D_/32, D_/32), t32>>>(wk, wkh, wkl, D_, D_);
    transpose_split<<<dim3(D_/32, D_/32), t32>>>(wv, wvh, wvl, D_, D_);
    transpose_split<<<dim3(D_/32, D_/32), t32>>>(wo, woh, wol, D_, D_);
    transpose_split<<<dim3(F_/32, D_/32), t32>>>(w1, w1h, w1l, D_, F_);
    transpose_split<<<dim3(D_/32, F_/32), t32>>>(w2, w2h, w2l, F_, D_);

    dim3 gD(D_/128, M_/128);     // 8 x 32
    dim3 gF(F_/128, M_/128);     // 32 x 32

    // QKV projections (HMMA tensor core)
    hmma_gemm<0,0><<<gD, blk, GEMM_SMEM>>>(xh, xl, wqh, wql, bq, Q, nullptr, nullptr, M_, D_, D_);
    hmma_gemm<0,0><<<gD, blk, GEMM_SMEM>>>(xh, xl, wkh, wkl, bk, K, nullptr, nullptr, M_, D_, D_);
    hmma_gemm<0,0><<<gD, blk, GEMM_SMEM>>>(xh, xl, wvh, wvl, bv, V, nullptr, nullptr, M_, D_, D_);

    // attention
    dim3 gA(S_/64, B_*H_);
    attn_kernel<<<gA, blk>>>(Q, K, V, mask, ATT);

    // output projection + residual LN1
    split_bf16<<<(M_*D_/4 + 255)/256, blk>>>(ATT, ath, atl, M_*D_/4);
    hmma_gemm<0,0><<<gD, blk, GEMM_SMEM>>>(ath, atl, woh, wol, bo, PROJ, nullptr, nullptr, M_, D_, D_);
    add_ln_kernel<<<M_, blk>>>(x, PROJ, g1, b1, H1);

    // FFN: GEMM1 (GELU, bf16 split out) -> GEMM2 -> residual LN2
    split_bf16<<<(M_*D_/4 + 255)/256, blk>>>(H1, h1h, h1l, M_*D_/4);
    hmma_gemm<1,1><<<gF, blk, GEMM_SMEM>>>(h1h, h1l, w1h, w1l, bf1, nullptr, f1h, f1l, M_, F_, D_);
    hmma_gemm<0,0><<<gD, blk, GEMM_SMEM>>>(f1h, f1l, w2h, w2l, bf2, FF2, nullptr, nullptr, M_, D_, F_);
    add_ln_kernel<<<M_, blk>>>(H1, FF2, g2, b2, out);
}

// round 14
// speedup vs baseline: 1.0005x; 1.0005x over previous
#include <cuda_runtime.h>
#include <cuda_bf16.h>
#include <math.h>
#include <stdint.h>

// Problem dims (fixed by reference)
#define B_ 2
#define S_ 2048
#define D_ 1024
#define H_ 16
#define W_ 64
#define F_ 4096
#define M_ (B_*S_)   // 4096 rows

// ============================ helpers ============================
__device__ __forceinline__ uint32_t smem_u32(const void* p) {
    uint32_t a;
    asm("{ .reg .u64 t; cvta.to.shared.u64 t, %1; cvt.u32.u64 %0, t; }" : "=r"(a) : "l"(p));
    return a;
}
__device__ __forceinline__ void cp16(uint32_t d, const void* g) {
    asm volatile("cp.async.cg.shared.global [%0], [%1], 16;" :: "r"(d), "l"(g));
}
#define CP_COMMIT() asm volatile("cp.async.commit_group;" ::: "memory")
#define CP_WAIT(N)  asm volatile("cp.async.wait_group %0;" :: "n"(N) : "memory")

__device__ __forceinline__ void ldsm4(uint32_t r[4], uint32_t addr) {
    asm volatile("ldmatrix.sync.aligned.m8n8.x4.shared.b16 {%0,%1,%2,%3}, [%4];"
        : "=r"(r[0]), "=r"(r[1]), "=r"(r[2]), "=r"(r[3]) : "r"(addr));
}
__device__ __forceinline__ void mma_bf16(float d[4], const uint32_t a[4], const uint32_t b[2]) {
    asm volatile("mma.sync.aligned.m16n8k16.row.col.f32.bf16.bf16.f32 "
        "{%0,%1,%2,%3},{%4,%5,%6,%7},{%8,%9},{%0,%1,%2,%3};"
        : "+f"(d[0]), "+f"(d[1]), "+f"(d[2]), "+f"(d[3])
        : "r"(a[0]), "r"(a[1]), "r"(a[2]), "r"(a[3]), "r"(b[0]), "r"(b[1]));
}

// -------- scratch (device globals; no runtime allocation allowed) --------
__device__ float          g_Q   [M_*D_];
__device__ float          g_K   [M_*D_];
__device__ float          g_V   [M_*D_];
__device__ float          g_ATT [M_*D_];
__device__ float          g_PROJ[M_*D_];
__device__ float          g_H1  [M_*D_];
__device__ float          g_FF2 [M_*D_];
__device__ __nv_bfloat16  g_xh  [M_*D_],  g_xl  [M_*D_];
__device__ __nv_bfloat16  g_atth[M_*D_],  g_attl[M_*D_];
__device__ __nv_bfloat16  g_h1h [M_*D_],  g_h1l [M_*D_];
__device__ __nv_bfloat16  g_ff1h[M_*F_],  g_ff1l[M_*F_];
__device__ __nv_bfloat16  g_wqh [D_*D_],  g_wql [D_*D_];
__device__ __nv_bfloat16  g_wkh [D_*D_],  g_wkl [D_*D_];
__device__ __nv_bfloat16  g_wvh [D_*D_],  g_wvl [D_*D_];
__device__ __nv_bfloat16  g_woh [D_*D_],  g_wol [D_*D_];
__device__ __nv_bfloat16  g_w1h [F_*D_],  g_w1l [F_*D_];
__device__ __nv_bfloat16  g_w2h [D_*F_],  g_w2l [D_*F_];

// ===========================================================================
// split fp32 -> (hi, lo) bf16 planes. 4 elements / thread.
// ===========================================================================
__global__ __launch_bounds__(256) void split_bf16(
    const float* __restrict__ x, __nv_bfloat16* __restrict__ h,
    __nv_bfloat16* __restrict__ l, int n4)
{
    int i = blockIdx.x * blockDim.x + threadIdx.x;
    if (i >= n4) return;
    float4 v = reinterpret_cast<const float4*>(x)[i];
    __nv_bfloat16 hv[4], lv[4];
    float vv[4] = {v.x, v.y, v.z, v.w};
#pragma unroll
    for (int t = 0; t < 4; t++) {
        hv[t] = __float2bfloat16(vv[t]);
        lv[t] = __float2bfloat16(vv[t] - __bfloat162float(hv[t]));
    }
    reinterpret_cast<uint2*>(h)[i] = *reinterpret_cast<uint2*>(hv);
    reinterpret_cast<uint2*>(l)[i] = *reinterpret_cast<uint2*>(lv);
}

// ===========================================================================
// transpose + split:  in fp32 [R,C] -> out bf16 [C,R]  (out[n][k] = in[k][n])
// ===========================================================================
__global__ void transpose_split(
    const float* __restrict__ in, __nv_bfloat16* __restrict__ oh,
    __nv_bfloat16* __restrict__ ol, int R, int C)
{
    __shared__ float t[32][33];
    int n0 = blockIdx.x * 32, k0 = blockIdx.y * 32;
    int tx = threadIdx.x, ty = threadIdx.y;
#pragma unroll
    for (int j = 0; j < 32; j += 8)
        t[ty + j][tx] = in[(size_t)(k0 + ty + j) * C + n0 + tx];
    __syncthreads();
#pragma unroll
    for (int j = 0; j < 32; j += 8) {
        float v = t[tx][ty + j];
        __nv_bfloat16 hv = __float2bfloat16(v);
        float r = v - __bfloat162float(hv);
        size_t o = (size_t)(n0 + ty + j) * R + k0 + tx;
        oh[o] = hv;
        ol[o] = __float2bfloat16(r);
    }
}

// ===========================================================================
// HMMA split-bf16 GEMM:  C[M,N] = A[M,K] @ B[N,K]^T + bias
// A as hi/lo bf16 K-major; B as hi/lo bf16 K-major (pre-transposed).
// C = AhBh + AhBl + AlBh  (fp32-grade accuracy, fp32 register accumulators)
// CTA tile 128x128, BK=32, 8 warps (warp tile 32x64), cp.async 2-stage.
// ACT=1: exact-erf GELU.  OUTB=1: write bf16 hi/lo planes; else fp32.
// ===========================================================================
#define TILE_B 10240          // 128 rows * 80 bytes (32 bf16 + 8 pad)
#define STAGE_B (4*TILE_B)    // Ah, Al, Bh, Bl
#define GEMM_SMEM (2*STAGE_B) // 81920

template<int ACT, int OUTB>
__global__ __launch_bounds__(256) void hmma_gemm(
    const __nv_bfloat16* __restrict__ Ah, const __nv_bfloat16* __restrict__ Al,
    const __nv_bfloat16* __restrict__ Bh, const __nv_bfloat16* __restrict__ Bl,
    const float* __restrict__ bias,
    float* __restrict__ Cf, __nv_bfloat16* __restrict__ Chi, __nv_bfloat16* __restrict__ Clo,
    int M, int N, int K)
{
    extern __shared__ char sm[];
    __shared__ float bias_s[128];

    const int tid  = threadIdx.x;
    const int lane = tid & 31;
    const int wid  = tid >> 5;
    const int wm   = wid & 3;      // 4 warps over M (32 rows each)
    const int wn   = wid >> 2;     // 2 warps over N (64 cols each)
    const int m0   = blockIdx.y * 128;
    const int n0   = blockIdx.x * 128;
    const uint32_t sbase = smem_u32(sm);

    if (tid < 128) bias_s[tid] = bias[n0 + tid];

    float d[2][8][4];
#pragma unroll
    for (int i = 0; i < 2; i++)
#pragma unroll
        for (int j = 0; j < 8; j++)
#pragma unroll
            for (int e = 0; e < 4; e++) d[i][j][e] = 0.f;

    const int NC = K >> 5;

    // ---- async stage loader: 4 tiles x 128 rows x 32 bf16 ----
    auto issue = [&](int kc, int s) {
        const int koff = kc * 32;
        const uint32_t st = sbase + s * STAGE_B;
#pragma unroll
        for (int i = 0; i < 2; i++) {
            int idx = tid + i * 256;           // 0..511
            int row = idx >> 2, c16 = idx & 3;
            uint32_t doff = (uint32_t)(row * 80 + c16 * 16);
            size_t ga = (size_t)(m0 + row) * K + koff + c16 * 8;
            size_t gb = (size_t)(n0 + row) * K + koff + c16 * 8;
            cp16(st + doff,              Ah + ga);
            cp16(st + TILE_B + doff,     Al + ga);
            cp16(st + 2 * TILE_B + doff, Bh + gb);
            cp16(st + 3 * TILE_B + doff, Bl + gb);
        }
        CP_COMMIT();
    };

    // ldmatrix lane address components
    const int aRow  = lane & 15;            // rows 0..15 of m16 tile
    const int aKsel = lane >> 4;            // k half
    const int bRow  = (lane & 7) + ((lane >> 4) << 3);  // n within 16-col group
    const int bKsel = (lane >> 3) & 1;      // k half

    auto compute = [&](int s) {
        const uint32_t st = sbase + s * STAGE_B;
#pragma unroll
        for (int kp = 0; kp < 2; kp++) {
            uint32_t ah[2][4], al[2][4], bh[8][2], bl[8][2];
            const uint32_t kcol = (uint32_t)((kp * 2) * 16);
#pragma unroll
            for (int i = 0; i < 2; i++) {
                uint32_t addr = st + (uint32_t)((wm * 32 + i * 16 + aRow) * 80) + kcol + (uint32_t)(aKsel * 16);
                ldsm4(ah[i], addr);
            }
#pragma unroll
            for (int g = 0; g < 4; g++) {
                uint32_t addr = st + 2 * TILE_B + (uint32_t)((wn * 64 + g * 16 + bRow) * 80) + kcol + (uint32_t)(bKsel * 16);
                uint32_t r[4];
                ldsm4(r, addr);
                bh[2*g][0] = r[0]; bh[2*g][1] = r[1];
                bh[2*g+1][0] = r[2]; bh[2*g+1][1] = r[3];
            }
            // pass 1: Ah * Bh
#pragma unroll
            for (int i = 0; i < 2; i++)
#pragma unroll
                for (int j = 0; j < 8; j++) mma_bf16(d[i][j], ah[i], bh[j]);
            // pass 2: Ah * Bl
#pragma unroll
            for (int g = 0; g < 4; g++) {
                uint32_t addr = st + 3 * TILE_B + (uint32_t)((wn * 64 + g * 16 + bRow) * 80) + kcol + (uint32_t)(bKsel * 16);
                uint32_t r[4];
                ldsm4(r, addr);
                bl[2*g][0] = r[0]; bl[2*g][1] = r[1];
                bl[2*g+1][0] = r[2]; bl[2*g+1][1] = r[3];
            }
#pragma unroll
            for (int i = 0; i < 2; i++)
#pragma unroll
                for (int j = 0; j < 8; j++) mma_bf16(d[i][j], ah[i], bl[j]);
            // pass 3: Al * Bh
#pragma unroll
            for (int i = 0; i < 2; i++) {
                uint32_t addr = st + TILE_B + (uint32_t)((wm * 32 + i * 16 + aRow) * 80) + kcol + (uint32_t)(aKsel * 16);
                ldsm4(al[i], addr);
            }
#pragma unroll
            for (int i = 0; i < 2; i++)
#pragma unroll
                for (int j = 0; j < 8; j++) mma_bf16(d[i][j], al[i], bh[j]);
        }
    };

    issue(0, 0);
    for (int kc = 0; kc < NC; kc++) {
        if (kc + 1 < NC) { issue(kc + 1, (kc + 1) & 1); CP_WAIT(1); }
        else             { CP_WAIT(0); }
        __syncthreads();
        compute(kc & 1);
        __syncthreads();
    }

    // ---- epilogue ----
#pragma unroll
    for (int i = 0; i < 2; i++) {
        const int r = m0 + wm * 32 + i * 16 + (lane >> 2);
#pragma unroll
        for (int j = 0; j < 8; j++) {
            const int cl = wn * 64 + j * 8 + 2 * (lane & 3);   // col within 128 tile
            const float b0 = bias_s[cl], b1 = bias_s[cl + 1];
            float v00 = d[i][j][0] + b0, v01 = d[i][j][1] + b1;
            float v10 = d[i][j][2] + b0, v11 = d[i][j][3] + b1;
            if (ACT == 1) {
                v00 = 0.5f * v00 * (1.f + erff(v00 * 0.7071067811865475f));
                v01 = 0.5f * v01 * (1.f + erff(v01 * 0.7071067811865475f));
                v10 = 0.5f * v10 * (1.f + erff(v10 * 0.7071067811865475f));
                v11 = 0.5f * v11 * (1.f + erff(v11 * 0.7071067811865475f));
            }
            const size_t o0 = (size_t)r * N + n0 + cl;
            const size_t o1 = (size_t)(r + 8) * N + n0 + cl;
            if (OUTB) {
                __nv_bfloat16 h00 = __float2bfloat16(v00);
                __nv_bfloat16 h01 = __float2bfloat16(v01);
                __nv_bfloat16 h10 = __float2bfloat16(v10);
                __nv_bfloat16 h11 = __float2bfloat16(v11);
                __nv_bfloat162 hp0; hp0.x = h00; hp0.y = h01;
                __nv_bfloat162 hp1; hp1.x = h10; hp1.y = h11;
                __nv_bfloat162 lp0; lp0.x = __float2bfloat16(v00 - __bfloat162float(h00));
                                    lp0.y = __float2bfloat16(v01 - __bfloat162float(h01));
                __nv_bfloat162 lp1; lp1.x = __float2bfloat16(v10 - __bfloat162float(h10));
                                    lp1.y = __float2bfloat16(v11 - __bfloat162float(h11));
                *reinterpret_cast<__nv_bfloat162*>(Chi + o0) = hp0;
                *reinterpret_cast<__nv_bfloat162*>(Chi + o1) = hp1;
                *reinterpret_cast<__nv_bfloat162*>(Clo + o0) = lp0;
                *reinterpret_cast<__nv_bfloat162*>(Clo + o1) = lp1;
            } else {
                *reinterpret_cast<float2*>(Cf + o0) = make_float2(v00, v01);
                *reinterpret_cast<float2*>(Cf + o1) = make_float2(v10, v11);
            }
        }
    }
}

// ===========================================================================
// Flash-style attention (fp32 SIMT), 2 CTAs/SM.
// ===========================================================================
__global__ __launch_bounds__(256, 2) void attn_kernel(
    const float* __restrict__ Q, const float* __restrict__ K,
    const float* __restrict__ V, const int* __restrict__ mask,
    float* __restrict__ O)
{
    __shared__ float k_s[64][68];
    __shared__ float v_s[64][68];
    __shared__ float madd[64];

    const int tid  = threadIdx.x;
    const int bh   = blockIdx.y;
    const int b    = bh / H_;
    const int h    = bh % H_;
    const int q0   = blockIdx.x * 64;
    const int row  = tid >> 2;
    const int quad = tid & 3;

    float qreg[16];
    {
        const float* qp = Q + (size_t)(b * S_ + q0 + row) * D_ + h * W_ + quad * 16;
#pragma unroll
        for (int t = 0; t < 16; t += 4) {
            float4 f = *reinterpret_cast<const float4*>(qp + t);
            qreg[t] = f.x; qreg[t+1] = f.y; qreg[t+2] = f.z; qreg[t+3] = f.w;
        }
    }

    float o[16];
#pragma unroll
    for (int t = 0; t < 16; t++) o[t] = 0.f;
    float m = -1e30f, l = 0.f;

    for (int kb = 0; kb < S_ / 64; kb++) {
#pragma unroll
        for (int i = 0; i < 16; i++) {
            int idx = tid + i * 256;
            int j = idx >> 6, w = idx & 63;
            size_t goff = (size_t)(b * S_ + kb * 64 + j) * D_ + h * W_ + w;
            k_s[j][w] = K[goff];
            v_s[j][w] = V[goff];
        }
        if (tid < 64)
            madd[tid] = -10000.f * (1.f - (float)mask[b * S_ + kb * 64 + tid]);
        __syncthreads();

#pragma unroll
        for (int c = 0; c < 4; c++) {
            float sj[16];
#pragma unroll
            for (int jj = 0; jj < 16; jj++) {
                int j = c * 16 + jj;
                const float* kr = &k_s[j][quad * 16];
                float pv = 0.f;
#pragma unroll
                for (int t = 0; t < 16; t += 4) {
                    float4 f = *reinterpret_cast<const float4*>(kr + t);
                    pv = fmaf(qreg[t],   f.x, pv);
                    pv = fmaf(qreg[t+1], f.y, pv);
                    pv = fmaf(qreg[t+2], f.z, pv);
                    pv = fmaf(qreg[t+3], f.w, pv);
                }
                pv += __shfl_xor_sync(0xffffffffu, pv, 1);
                pv += __shfl_xor_sync(0xffffffffu, pv, 2);
                sj[jj] = pv * 0.125f + madd[j];
            }
            float mn = m;
#pragma unroll
            for (int jj = 0; jj < 16; jj++) mn = fmaxf(mn, sj[jj]);
            float factor = __expf(m - mn);
            l *= factor;
#pragma unroll
            for (int t = 0; t < 16; t++) o[t] *= factor;
#pragma unroll
            for (int jj = 0; jj < 16; jj++) {
                float pv = __expf(sj[jj] - mn);
                l += pv;
                const float* vr = &v_s[c * 16 + jj][quad * 16];
#pragma unroll
                for (int t = 0; t < 16; t += 4) {
                    float4 f = *reinterpret_cast<const float4*>(vr + t);
                    o[t]   = fmaf(pv, f.x, o[t]);
                    o[t+1] = fmaf(pv, f.y, o[t+1]);
                    o[t+2] = fmaf(pv, f.z, o[t+2]);
                    o[t+3] = fmaf(pv, f.w, o[t+3]);
                }
            }
            m = mn;
        }
        __syncthreads();
    }

    float inv = 1.f / l;
    float* op = O + (size_t)(b * S_ + q0 + row) * D_ + h * W_ + quad * 16;
#pragma unroll
    for (int t = 0; t < 16; t++) op[t] = o[t] * inv;
}

// ===========================================================================
// Fused residual add + LayerNorm. One block (256 thr) per row of 1024.
// ===========================================================================
__global__ __launch_bounds__(256) void add_ln_kernel(
    const float* __restrict__ X, const float* __restrict__ Y,
    const float* __restrict__ gamma, const float* __restrict__ beta,
    float* __restrict__ out)
{
    const int rowbase = blockIdx.x * D_;
    const int tid = threadIdx.x;

    float4 x4 = *reinterpret_cast<const float4*>(X + rowbase + tid * 4);
    float4 y4 = *reinterpret_cast<const float4*>(Y + rowbase + tid * 4);
    float v0 = x4.x + y4.x, v1 = x4.y + y4.y, v2 = x4.z + y4.z, v3 = x4.w + y4.w;

    float s  = v0 + v1 + v2 + v3;
    float sq = v0*v0 + v1*v1 + v2*v2 + v3*v3;

    __shared__ float ssum[8], ssq[8];
#pragma unroll
    for (int off = 16; off; off >>= 1) {
        s  += __shfl_xor_sync(0xffffffffu, s,  off);
        sq += __shfl_xor_sync(0xffffffffu, sq, off);
    }
    int wid = tid >> 5, lane = tid & 31;
    if (lane == 0) { ssum[wid] = s; ssq[wid] = sq; }
    __syncthreads();
    if (tid == 0) {
        float ts = 0.f, tq = 0.f;
#pragma unroll
        for (int i = 0; i < 8; i++) { ts += ssum[i]; tq += ssq[i]; }
        ssum[0] = ts; ssq[0] = tq;
    }
    __syncthreads();

    float mean = ssum[0] * (1.f / D_);
    float var  = ssq[0]  * (1.f / D_) - mean * mean;
    float inv  = rsqrtf(var + 1e-12f);

    float4 g4 = *reinterpret_cast<const float4*>(gamma + tid * 4);
    float4 b4 = *reinterpret_cast<const float4*>(beta  + tid * 4);
    float4 r;
    r.x = g4.x * (v0 - mean) * inv + b4.x;
    r.y = g4.y * (v1 - mean) * inv + b4.y;
    r.z = g4.z * (v2 - mean) * inv + b4.z;
    r.w = g4.w * (v3 - mean) * inv + b4.w;
    *reinterpret_cast<float4*>(out + rowbase + tid * 4) = r;
}

// ===========================================================================
// Launch
// ===========================================================================
template<typename T>
static T* symAddr(const void* sym)
{
    void* p = nullptr;
    cudaGetSymbolAddress(&p, sym);
    return (T*)p;
}

extern "C" void kernel_launch(void* const* d_in, const int* in_sizes, int n_in,
                              void* d_out, int out_size)
{
    const float* x    = (const float*)d_in[0];
    const int*   mask = (const int*)  d_in[1];
    const float* wq   = (const float*)d_in[2];
    const float* bq   = (const float*)d_in[3];
    const float* wk   = (const float*)d_in[4];
    const float* bk   = (const float*)d_in[5];
    const float* wv   = (const float*)d_in[6];
    const float* bv   = (const float*)d_in[7];
    const float* wo   = (const float*)d_in[8];
    const float* bo   = (const float*)d_in[9];
    const float* g1   = (const float*)d_in[10];
    const float* b1   = (const float*)d_in[11];
    const float* w1   = (const float*)d_in[12];
    const float* bf1  = (const float*)d_in[13];
    const float* w2   = (const float*)d_in[14];
    const float* bf2  = (const float*)d_in[15];
    const float* g2   = (const float*)d_in[16];
    const float* b2   = (const float*)d_in[17];
    float* out = (float*)d_out;

    float* Q    = symAddr<float>(g_Q);
    float* K    = symAddr<float>(g_K);
    float* V    = symAddr<float>(g_V);
    float* ATT  = symAddr<float>(g_ATT);
    float* PROJ = symAddr<float>(g_PROJ);
    float* H1   = symAddr<float>(g_H1);
    float* FF2  = symAddr<float>(g_FF2);
    __nv_bfloat16 *xh  = symAddr<__nv_bfloat16>(g_xh),  *xl  = symAddr<__nv_bfloat16>(g_xl);
    __nv_bfloat16 *ath = symAddr<__nv_bfloat16>(g_atth),*atl = symAddr<__nv_bfloat16>(g_attl);
    __nv_bfloat16 *h1h = symAddr<__nv_bfloat16>(g_h1h), *h1l = symAddr<__nv_bfloat16>(g_h1l);
    __nv_bfloat16 *f1h = symAddr<__nv_bfloat16>(g_ff1h),*f1l = symAddr<__nv_bfloat16>(g_ff1l);
    __nv_bfloat16 *wqh = symAddr<__nv_bfloat16>(g_wqh), *wql = symAddr<__nv_bfloat16>(g_wql);
    __nv_bfloat16 *wkh = symAddr<__nv_bfloat16>(g_wkh), *wkl = symAddr<__nv_bfloat16>(g_wkl);
    __nv_bfloat16 *wvh = symAddr<__nv_bfloat16>(g_wvh), *wvl = symAddr<__nv_bfloat16>(g_wvl);
    __nv_bfloat16 *woh = symAddr<__nv_bfloat16>(g_woh), *wol = symAddr<__nv_bfloat16>(g_wol);
    __nv_bfloat16 *w1h = symAddr<__nv_bfloat16>(g_w1h), *w1l = symAddr<__nv_bfloat16>(g_w1l);
    __nv_bfloat16 *w2h = symAddr<__nv_bfloat16>(g_w2h), *w2l = symAddr<__nv_bfloat16>(g_w2l);

    cudaFuncSetAttribute(hmma_gemm<0,0>, cudaFuncAttributeMaxDynamicSharedMemorySize, GEMM_SMEM);
    cudaFuncSetAttribute(hmma_gemm<1,1>, cudaFuncAttributeMaxDynamicSharedMemorySize, GEMM_SMEM);

    dim3 blk(256);
    dim3 t32(32, 8);

    // input / weight conversions
    split_bf16<<<(M_*D_/4 + 255)/256, blk>>>(x, xh, xl, M_*D_/4);
    transpose_split<<<dim3(D_/32, D_/32), t32>>>(wq, wqh, wql, D_, D_);
    transpose_split<<<dim3(D_/32, D_/32), t32>>>(wk, wkh, wkl, D_, D_);
    transpose_split<<<dim3(D_/32, D_/32), t32>>>(wv, wvh, wvl, D_, D_);
    transpose_split<<<dim3(D_/32, D_/32), t32>>>(wo, woh, wol, D_, D_);
    transpose_split<<<dim3(F_/32, D_/32), t32>>>(w1, w1h, w1l, D_, F_);
    transpose_split<<<dim3(D_/32, F_/32), t32>>>(w2, w2h, w2l, F_, D_);

    dim3 gD(D_/128, M_/128);     // 8 x 32
    dim3 gF(F_/128, M_/128);     // 32 x 32

    // QKV projections (HMMA tensor core)
    hmma_gemm<0,0><<<gD, blk, GEMM_SMEM>>>(xh, xl, wqh, wql, bq, Q, nullptr, nullptr, M_, D_, D_);
    hmma_gemm<0,0><<<gD, blk, GEMM_SMEM>>>(xh, xl, wkh, wkl, bk, K, nullptr, nullptr, M_, D_, D_);
    hmma_gemm<0,0><<<gD, blk, GEMM_SMEM>>>(xh, xl, wvh, wvl, bv, V, nullptr, nullptr, M_, D_, D_);

    // attention
    dim3 gA(S_/64, B_*H_);
    attn_kernel<<<gA, blk>>>(Q, K, V, mask, ATT);

    // output projection + residual LN1
    split_bf16<<<(M_*D_/4 + 255)/256, blk>>>(ATT, ath, atl, M_*D_/4);
    hmma_gemm<0,0><<<gD, blk, GEMM_SMEM>>>(ath, atl, woh, wol, bo, PROJ, nullptr, nullptr, M_, D_, D_);
    add_ln_kernel<<<M_, blk>>>(x, PROJ, g1, b1, H1);

    // FFN: GEMM1 (GELU, bf16 split out) -> GEMM2 -> residual LN2
    split_bf16<<<(M_*D_/4 + 255)/256, blk>>>(H1, h1h, h1l, M_*D_/4);
    hmma_gemm<1,1><<<gF, blk, GEMM_SMEM>>>(h1h, h1l, w1h, w1l, bf1, nullptr, f1h, f1l, M_, F_, D_);
    hmma_gemm<0,0><<<gD, blk, GEMM_SMEM>>>(f1h, f1l, w2h, w2l, bf2, FF2, nullptr, nullptr, M_, D_, F_);
    add_ln_kernel<<<M_, blk>>>(H1, FF2, g2, b2, out);
}